// round 4
// baseline (speedup 1.0000x reference)
#include <cuda_runtime.h>

#define IS      256
#define TILE    16
#define NTX     (IS / TILE)      // 16 tiles per dim
#define FACES   4096
#define NBATCH  4
#define NEAR_P  0.1f
#define FAR_P   100.0f
#define TINYF   1e-12f
#define EPSV    0.001f
#define BINCAP  1024
#define NBINS   (NBATCH * NTX * NTX)   // 1024

__device__ float4 g_c0[NBATCH * FACES];
__device__ float4 g_c1[NBATCH * FACES];
__device__ float4 g_c2[NBATCH * FACES];
__device__ int    g_binCnt[NBINS];          // zero-init at load; raster re-zeros
__device__ int    g_binList[NBINS * BINCAP];

__global__ __launch_bounds__(256) void setup_kernel(const float* __restrict__ faces)
{
    const int id = blockIdx.x * 256 + threadIdx.x;   // 0 .. B*F-1
    const int b  = id >> 12;
    const int f  = id & (FACES - 1);

    const float* fv = faces + (size_t)id * 9;
    const float x0 = fv[0], y0 = fv[1], z0 = fv[2];
    const float x1 = fv[3], y1 = fv[4], z1 = fv[5];
    const float x2 = fv[6], y2 = fv[7], z2 = fv[8];

    g_c0[id] = make_float4(y1 - y2, x2 - x1, x1 * y2 - x2 * y1, 1.0f / z0);
    g_c1[id] = make_float4(y2 - y0, x0 - x2, x2 * y0 - x0 * y2, 1.0f / z1);
    g_c2[id] = make_float4(y0 - y1, x1 - x0, x0 * y1 - x1 * y0, 1.0f / z2);

    const float xmn = fminf(x0, fminf(x1, x2)), xmx = fmaxf(x0, fmaxf(x1, x2));
    const float ymn = fminf(y0, fminf(y1, y2)), ymx = fmaxf(y0, fmaxf(y1, y2));

    // pixel center xp = (2*px + 1 - IS)/IS  =>  px = (IS*xp + IS-1)/2 ; widen 1px
    int pxlo = (int)ceilf ((xmn * IS + (IS - 1)) * 0.5f) - 1;
    int pxhi = (int)floorf((xmx * IS + (IS - 1)) * 0.5f) + 1;
    int pylo = (int)ceilf ((ymn * IS + (IS - 1)) * 0.5f) - 1;
    int pyhi = (int)floorf((ymx * IS + (IS - 1)) * 0.5f) + 1;
    pxlo = max(pxlo, 0); pxhi = min(pxhi, IS - 1);
    pylo = max(pylo, 0); pyhi = min(pyhi, IS - 1);
    if (pxlo > pxhi || pylo > pyhi) return;

    const int txlo = pxlo >> 4, txhi = pxhi >> 4;
    const int tylo = pylo >> 4, tyhi = pyhi >> 4;
    for (int ty = tylo; ty <= tyhi; ty++)
        for (int tx = txlo; tx <= txhi; tx++) {
            const int bin = (b * NTX + ty) * NTX + tx;
            const int pos = atomicAdd(&g_binCnt[bin], 1);
            if (pos < BINCAP) g_binList[bin * BINCAP + pos] = f;
        }
}

__global__ __launch_bounds__(256) void raster_kernel(
    const float* __restrict__ faces,
    const float* __restrict__ tex,
    float* __restrict__ out)
{
    __shared__ float4 sc0[256], sc1[256], sc2[256];
    __shared__ int    sidx[256];
    __shared__ int    sn;

    const int tid = threadIdx.x;
    const int b   = blockIdx.z;
    const int px  = blockIdx.x * TILE + (tid & 15);
    const int py  = blockIdx.y * TILE + (tid >> 4);

    const float xp = (2.0f * px + 1.0f - IS) * (1.0f / IS);
    const float yp = (2.0f * py + 1.0f - IS) * (1.0f / IS);

    const int bin = (b * NTX + blockIdx.y) * NTX + blockIdx.x;
    if (tid == 0) {
        const int cnt = g_binCnt[bin];
        sn = min(cnt, BINCAP);
        g_binCnt[bin] = 0;                 // reset for the next graph replay
    }
    __syncthreads();
    const int n = sn;

    float bestInv = 0.0f;
    int   bestF   = -1;

    for (int start = 0; start < n; start += 256) {
        const int cnt = min(256, n - start);
        if (start) __syncthreads();
        if (tid < cnt) {
            const int f  = g_binList[bin * BINCAP + start + tid];
            const int id = b * FACES + f;
            sc0[tid] = g_c0[id];
            sc1[tid] = g_c1[id];
            sc2[tid] = g_c2[id];
            sidx[tid] = f;
        }
        __syncthreads();

        for (int c = 0; c < cnt; c++) {
            const float4 a0 = sc0[c];
            const float4 a1 = sc1[c];
            const float4 a2 = sc2[c];
            const float w0 = fmaf(xp, a0.x, fmaf(yp, a0.y, a0.z));
            const float w1 = fmaf(xp, a1.x, fmaf(yp, a1.y, a1.z));
            const float w2 = fmaf(xp, a2.x, fmaf(yp, a2.y, a2.z));
            const float det = w0 + w1 + w2;
            const bool inside = (fabsf(det) > TINYF) &&
                ((w0 > 0.f && w1 > 0.f && w2 > 0.f) ||
                 (w0 < 0.f && w1 < 0.f && w2 < 0.f));
            if (inside) {
                const float num = w0 * a0.w + w1 * a1.w + w2 * a2.w;
                float inv = num / det;              // = 1/zp, positive when inside
                if (!(fabsf(inv) > TINYF)) inv = 1.0f;
                if (inv > (1.0f / FAR_P) && inv < (1.0f / NEAR_P)) {
                    const int f = sidx[c];
                    if (inv > bestInv || (inv == bestInv && f < bestF)) {
                        bestInv = inv;
                        bestF   = f;
                    }
                }
            }
        }
    }

    // -------- shading --------
    float r = 0.f, g = 0.f, bl = 0.f, alpha = 0.f, depth = FAR_P;
    if (bestF >= 0) {
        const float* fv = faces + ((size_t)b * FACES + bestF) * 9;
        const float x0 = fv[0], y0 = fv[1], z0 = fv[2];
        const float x1 = fv[3], y1 = fv[4], z1 = fv[5];
        const float x2 = fv[6], y2 = fv[7], z2 = fv[8];

        const float w0 = yp * (x2 - x1) + xp * (y1 - y2) + (x1 * y2 - x2 * y1);
        const float w1 = yp * (x0 - x2) + xp * (y2 - y0) + (x2 * y0 - x0 * y2);
        const float w2 = yp * (x1 - x0) + xp * (y0 - y1) + (x0 * y1 - x1 * y0);
        float det = w0 + w1 + w2;
        if (!(fabsf(det) > TINYF)) det = 1.0f;
        float n0 = w0 / det, n1 = w1 / det, n2 = w2 / det;
        n0 = fminf(fmaxf(n0, 0.f), 1.f);
        n1 = fminf(fmaxf(n1, 0.f), 1.f);
        n2 = fminf(fmaxf(n2, 0.f), 1.f);
        float s = n0 + n1 + n2;
        if (!(s > TINYF)) s = 1.0f;
        n0 /= s; n1 /= s; n2 /= s;
        float invz = n0 / z0 + n1 / z1 + n2 / z2;
        if (!(fabsf(invz) > TINYF)) invz = 1.0f;
        const float zp = 1.0f / invz;
        depth = zp;
        alpha = 1.0f;

        const float hi = 3.0f - EPSV;   // T-1-EPS, T=4
        const float t0 = fminf(fmaxf(n0 * 3.0f * zp / z0, 0.f), hi);
        const float t1 = fminf(fmaxf(n1 * 3.0f * zp / z1, 0.f), hi);
        const float t2 = fminf(fmaxf(n2 * 3.0f * zp / z2, 0.f), hi);
        const float l0f = floorf(t0), l1f = floorf(t1), l2f = floorf(t2);
        const float f0 = t0 - l0f, f1 = t1 - l1f, f2 = t2 - l2f;
        const int l0 = (int)l0f, l1 = (int)l1f, l2 = (int)l2f;

        const float* tp = tex + ((size_t)b * FACES + bestF) * 192;
        #pragma unroll
        for (int d0 = 0; d0 < 2; d0++) {
            const float wx = d0 ? f0 : 1.0f - f0;
            #pragma unroll
            for (int d1 = 0; d1 < 2; d1++) {
                const float wy = wx * (d1 ? f1 : 1.0f - f1);
                #pragma unroll
                for (int d2 = 0; d2 < 2; d2++) {
                    const float wgt = wy * (d2 ? f2 : 1.0f - f2);
                    const int idx = ((l0 + d0) * 16 + (l1 + d1) * 4 + (l2 + d2)) * 3;
                    r  += wgt * tp[idx + 0];
                    g  += wgt * tp[idx + 1];
                    bl += wgt * tp[idx + 2];
                }
            }
        }
    }

    float* o = out + (((size_t)b * IS + py) * IS + px) * 5;
    o[0] = r; o[1] = g; o[2] = bl; o[3] = alpha; o[4] = depth;
}

extern "C" void kernel_launch(void* const* d_in, const int* in_sizes, int n_in,
                              void* d_out, int out_size)
{
    const float* faces = (const float*)d_in[0];
    const float* tex   = (const float*)d_in[1];
    float* out         = (float*)d_out;

    setup_kernel<<<(NBATCH * FACES) / 256, 256>>>(faces);
    dim3 grid(NTX, NTX, NBATCH);
    raster_kernel<<<grid, 256>>>(faces, tex, out);
}

// round 5
// speedup vs baseline: 1.0575x; 1.0575x over previous
#include <cuda_runtime.h>

#define IS      256
#define TILE    16
#define NTX     (IS / TILE)      // 16 tiles per dim
#define FACES   4096
#define NBATCH  4
#define NEAR_P  0.1f
#define FAR_P   100.0f
#define TINYF   1e-12f
#define EPSV    0.001f
#define BINCAP  2048
#define NBINS   (NBATCH * NTX * NTX)   // 1024

// Per-face precomputed, normalized by det:
//   g_c0 = (nA0, nB0, nC0, P)
//   g_c1 = (nA1, nB1, nC1, Q)
//   g_c2 = (nA2, nB2, nC2, R)
// n_i(x,y) = nA_i*x + nB_i*y + nC_i   (== w_i/det)
// inv_zp(x,y) = P*x + Q*y + R         (== (w0/z0+w1/z1+w2/z2)/det)
__device__ float4 g_c0[NBATCH * FACES];
__device__ float4 g_c1[NBATCH * FACES];
__device__ float4 g_c2[NBATCH * FACES];
__device__ int    g_binCnt[NBINS];          // zero-init at load; raster re-zeros
__device__ int    g_binList[NBINS * BINCAP];

__global__ __launch_bounds__(256) void setup_kernel(const float* __restrict__ faces)
{
    const int id = blockIdx.x * 256 + threadIdx.x;   // 0 .. B*F-1
    const int b  = id >> 12;
    const int f  = id & (FACES - 1);

    const float* fv = faces + (size_t)id * 9;
    const float x0 = fv[0], y0 = fv[1], z0 = fv[2];
    const float x1 = fv[3], y1 = fv[4], z1 = fv[5];
    const float x2 = fv[6], y2 = fv[7], z2 = fv[8];

    const float A0 = y1 - y2, B0 = x2 - x1, C0 = x1 * y2 - x2 * y1;
    const float A1 = y2 - y0, B1 = x0 - x2, C1 = x2 * y0 - x0 * y2;
    const float A2 = y0 - y1, B2 = x1 - x0, C2 = x0 * y1 - x1 * y0;
    const float det = C0 + C1 + C2;      // x/y coeffs cancel: det is constant
    if (!(fabsf(det) > TINYF)) return;   // degenerate: can never pass inside test

    const float rd  = 1.0f / det;
    const float rz0 = 1.0f / z0, rz1 = 1.0f / z1, rz2 = 1.0f / z2;
    const float nA0 = A0 * rd, nB0 = B0 * rd, nC0 = C0 * rd;
    const float nA1 = A1 * rd, nB1 = B1 * rd, nC1 = C1 * rd;
    const float nA2 = A2 * rd, nB2 = B2 * rd, nC2 = C2 * rd;
    const float P = nA0 * rz0 + nA1 * rz1 + nA2 * rz2;
    const float Q = nB0 * rz0 + nB1 * rz1 + nB2 * rz2;
    const float R = nC0 * rz0 + nC1 * rz1 + nC2 * rz2;

    g_c0[id] = make_float4(nA0, nB0, nC0, P);
    g_c1[id] = make_float4(nA1, nB1, nC1, Q);
    g_c2[id] = make_float4(nA2, nB2, nC2, R);

    const float xmn = fminf(x0, fminf(x1, x2)), xmx = fmaxf(x0, fmaxf(x1, x2));
    const float ymn = fminf(y0, fminf(y1, y2)), ymx = fmaxf(y0, fmaxf(y1, y2));

    // pixel center xp = (2*px + 1 - IS)/IS  =>  px = (IS*xp + IS-1)/2 ; widen 1px
    int pxlo = (int)ceilf ((xmn * IS + (IS - 1)) * 0.5f) - 1;
    int pxhi = (int)floorf((xmx * IS + (IS - 1)) * 0.5f) + 1;
    int pylo = (int)ceilf ((ymn * IS + (IS - 1)) * 0.5f) - 1;
    int pyhi = (int)floorf((ymx * IS + (IS - 1)) * 0.5f) + 1;
    pxlo = max(pxlo, 0); pxhi = min(pxhi, IS - 1);
    pylo = max(pylo, 0); pyhi = min(pyhi, IS - 1);
    if (pxlo > pxhi || pylo > pyhi) return;

    const int txlo = pxlo >> 4, txhi = pxhi >> 4;
    const int tylo = pylo >> 4, tyhi = pyhi >> 4;
    for (int ty = tylo; ty <= tyhi; ty++)
        for (int tx = txlo; tx <= txhi; tx++) {
            const int bin = (b * NTX + ty) * NTX + tx;
            const int pos = atomicAdd(&g_binCnt[bin], 1);
            if (pos < BINCAP) g_binList[bin * BINCAP + pos] = f;
        }
}

__global__ __launch_bounds__(256) void raster_kernel(
    const float* __restrict__ faces,
    const float* __restrict__ tex,
    float* __restrict__ out)
{
    __shared__ float4 sc0[256], sc1[256], sc2[256];
    __shared__ int    sidx[256];
    __shared__ int    sn;

    const int tid = threadIdx.x;
    const int b   = blockIdx.z;
    const int px  = blockIdx.x * TILE + (tid & 15);
    const int py  = blockIdx.y * TILE + (tid >> 4);

    const float xp = (2.0f * px + 1.0f - IS) * (1.0f / IS);
    const float yp = (2.0f * py + 1.0f - IS) * (1.0f / IS);

    const int bin = (b * NTX + blockIdx.y) * NTX + blockIdx.x;
    if (tid == 0) {
        const int cnt = g_binCnt[bin];
        sn = min(cnt, BINCAP);
        g_binCnt[bin] = 0;                 // reset for the next graph replay
    }
    __syncthreads();
    const int n = sn;

    float bestInv = 0.0f;
    int   bestF   = -1;

    for (int start = 0; start < n; start += 256) {
        const int cnt = min(256, n - start);
        if (start) __syncthreads();
        if (tid < cnt) {
            const int f  = g_binList[bin * BINCAP + start + tid];
            const int id = b * FACES + f;
            sc0[tid] = g_c0[id];
            sc1[tid] = g_c1[id];
            sc2[tid] = g_c2[id];
            sidx[tid] = f;
        }
        __syncthreads();

        #pragma unroll 2
        for (int c = 0; c < cnt; c++) {
            const float4 a0 = sc0[c];
            const float4 a1 = sc1[c];
            const float4 a2 = sc2[c];
            const float n0 = fmaf(xp, a0.x, fmaf(yp, a0.y, a0.z));
            const float n1 = fmaf(xp, a1.x, fmaf(yp, a1.y, a1.z));
            const float n2 = fmaf(xp, a2.x, fmaf(yp, a2.y, a2.z));
            const float iz = fmaf(xp, a0.w, fmaf(yp, a1.w, a2.w));
            const float mn = fminf(n0, fminf(n1, n2));
            // inside (all normalized weights strictly >0) + near/far clip on zp=1/iz
            if (mn > 0.0f && iz > (1.0f / FAR_P) && iz < (1.0f / NEAR_P)) {
                const int f = sidx[c];
                if (iz > bestInv || (iz == bestInv && f < bestF)) {
                    bestInv = iz;
                    bestF   = f;
                }
            }
        }
    }

    // -------- shading (mirrors reference _bary exactly) --------
    float r = 0.f, g = 0.f, bl = 0.f, alpha = 0.f, depth = FAR_P;
    if (bestF >= 0) {
        const float* fv = faces + ((size_t)b * FACES + bestF) * 9;
        const float x0 = fv[0], y0 = fv[1], z0 = fv[2];
        const float x1 = fv[3], y1 = fv[4], z1 = fv[5];
        const float x2 = fv[6], y2 = fv[7], z2 = fv[8];

        const float w0 = yp * (x2 - x1) + xp * (y1 - y2) + (x1 * y2 - x2 * y1);
        const float w1 = yp * (x0 - x2) + xp * (y2 - y0) + (x2 * y0 - x0 * y2);
        const float w2 = yp * (x1 - x0) + xp * (y0 - y1) + (x0 * y1 - x1 * y0);
        float det = w0 + w1 + w2;
        if (!(fabsf(det) > TINYF)) det = 1.0f;
        float n0 = w0 / det, n1 = w1 / det, n2 = w2 / det;
        n0 = fminf(fmaxf(n0, 0.f), 1.f);
        n1 = fminf(fmaxf(n1, 0.f), 1.f);
        n2 = fminf(fmaxf(n2, 0.f), 1.f);
        float s = n0 + n1 + n2;
        if (!(s > TINYF)) s = 1.0f;
        n0 /= s; n1 /= s; n2 /= s;
        float invz = n0 / z0 + n1 / z1 + n2 / z2;
        if (!(fabsf(invz) > TINYF)) invz = 1.0f;
        const float zp = 1.0f / invz;
        depth = zp;
        alpha = 1.0f;

        const float hi = 3.0f - EPSV;   // T-1-EPS, T=4
        const float t0 = fminf(fmaxf(n0 * 3.0f * zp / z0, 0.f), hi);
        const float t1 = fminf(fmaxf(n1 * 3.0f * zp / z1, 0.f), hi);
        const float t2 = fminf(fmaxf(n2 * 3.0f * zp / z2, 0.f), hi);
        const float l0f = floorf(t0), l1f = floorf(t1), l2f = floorf(t2);
        const float f0 = t0 - l0f, f1 = t1 - l1f, f2 = t2 - l2f;
        const int l0 = (int)l0f, l1 = (int)l1f, l2 = (int)l2f;

        const float* tp = tex + ((size_t)b * FACES + bestF) * 192;
        #pragma unroll
        for (int d0 = 0; d0 < 2; d0++) {
            const float wx = d0 ? f0 : 1.0f - f0;
            #pragma unroll
            for (int d1 = 0; d1 < 2; d1++) {
                const float wy = wx * (d1 ? f1 : 1.0f - f1);
                #pragma unroll
                for (int d2 = 0; d2 < 2; d2++) {
                    const float wgt = wy * (d2 ? f2 : 1.0f - f2);
                    const int idx = ((l0 + d0) * 16 + (l1 + d1) * 4 + (l2 + d2)) * 3;
                    r  += wgt * tp[idx + 0];
                    g  += wgt * tp[idx + 1];
                    bl += wgt * tp[idx + 2];
                }
            }
        }
    }

    float* o = out + (((size_t)b * IS + py) * IS + px) * 5;
    o[0] = r; o[1] = g; o[2] = bl; o[3] = alpha; o[4] = depth;
}

extern "C" void kernel_launch(void* const* d_in, const int* in_sizes, int n_in,
                              void* d_out, int out_size)
{
    const float* faces = (const float*)d_in[0];
    const float* tex   = (const float*)d_in[1];
    float* out         = (float*)d_out;

    setup_kernel<<<(NBATCH * FACES) / 256, 256>>>(faces);
    dim3 grid(NTX, NTX, NBATCH);
    raster_kernel<<<grid, 256>>>(faces, tex, out);
}

// round 6
// speedup vs baseline: 1.1817x; 1.1174x over previous
#include <cuda_runtime.h>

#define IS      256
#define TILE    8
#define NTX     (IS / TILE)      // 32 tiles per dim
#define FACES   4096
#define NBATCH  4
#define NEAR_P  0.1f
#define FAR_P   100.0f
#define TINYF   1e-12f
#define EPSV    0.001f
#define BINCAP  256
#define NBINS   (NBATCH * NTX * NTX)   // 4096

// Per-face precomputed, normalized by det:
//   g_c0 = (nA0, nB0, nC0, P)
//   g_c1 = (nA1, nB1, nC1, Q)
//   g_c2 = (nA2, nB2, nC2, R)
// n_i(x,y) = nA_i*x + nB_i*y + nC_i   (== w_i/det)
// inv_zp(x,y) = P*x + Q*y + R
__device__ float4 g_c0[NBATCH * FACES];
__device__ float4 g_c1[NBATCH * FACES];
__device__ float4 g_c2[NBATCH * FACES];
__device__ int    g_binCnt[NBINS];          // zero-init at load; raster re-zeros
__device__ int    g_binList[NBINS * BINCAP];

__global__ __launch_bounds__(256) void setup_kernel(const float* __restrict__ faces)
{
    const int id = blockIdx.x * 256 + threadIdx.x;   // 0 .. B*F-1
    const int b  = id >> 12;
    const int f  = id & (FACES - 1);

    const float* fv = faces + (size_t)id * 9;
    const float x0 = fv[0], y0 = fv[1], z0 = fv[2];
    const float x1 = fv[3], y1 = fv[4], z1 = fv[5];
    const float x2 = fv[6], y2 = fv[7], z2 = fv[8];

    const float A0 = y1 - y2, B0 = x2 - x1, C0 = x1 * y2 - x2 * y1;
    const float A1 = y2 - y0, B1 = x0 - x2, C1 = x2 * y0 - x0 * y2;
    const float A2 = y0 - y1, B2 = x1 - x0, C2 = x0 * y1 - x1 * y0;
    const float det = C0 + C1 + C2;      // x/y coeffs cancel: det is constant
    if (!(fabsf(det) > TINYF)) return;   // degenerate: can never pass inside test

    const float rd  = 1.0f / det;
    const float rz0 = 1.0f / z0, rz1 = 1.0f / z1, rz2 = 1.0f / z2;
    const float nA0 = A0 * rd, nB0 = B0 * rd, nC0 = C0 * rd;
    const float nA1 = A1 * rd, nB1 = B1 * rd, nC1 = C1 * rd;
    const float nA2 = A2 * rd, nB2 = B2 * rd, nC2 = C2 * rd;
    const float P = nA0 * rz0 + nA1 * rz1 + nA2 * rz2;
    const float Q = nB0 * rz0 + nB1 * rz1 + nB2 * rz2;
    const float R = nC0 * rz0 + nC1 * rz1 + nC2 * rz2;

    g_c0[id] = make_float4(nA0, nB0, nC0, P);
    g_c1[id] = make_float4(nA1, nB1, nC1, Q);
    g_c2[id] = make_float4(nA2, nB2, nC2, R);

    const float xmn = fminf(x0, fminf(x1, x2)), xmx = fmaxf(x0, fmaxf(x1, x2));
    const float ymn = fminf(y0, fminf(y1, y2)), ymx = fmaxf(y0, fmaxf(y1, y2));

    // pixel center xp = (2*px + 1 - IS)/IS  =>  px = (IS*xp + IS-1)/2 ; widen 1px
    int pxlo = (int)ceilf ((xmn * IS + (IS - 1)) * 0.5f) - 1;
    int pxhi = (int)floorf((xmx * IS + (IS - 1)) * 0.5f) + 1;
    int pylo = (int)ceilf ((ymn * IS + (IS - 1)) * 0.5f) - 1;
    int pyhi = (int)floorf((ymx * IS + (IS - 1)) * 0.5f) + 1;
    pxlo = max(pxlo, 0); pxhi = min(pxhi, IS - 1);
    pylo = max(pylo, 0); pyhi = min(pyhi, IS - 1);
    if (pxlo > pxhi || pylo > pyhi) return;

    // conservative per-edge cull margins (scale with coefficient magnitude)
    const float m0e = -1e-5f * (fabsf(nA0) + fabsf(nB0)) - 1e-6f;
    const float m1e = -1e-5f * (fabsf(nA1) + fabsf(nB1)) - 1e-6f;
    const float m2e = -1e-5f * (fabsf(nA2) + fabsf(nB2)) - 1e-6f;

    const int txlo = pxlo >> 3, txhi = pxhi >> 3;
    const int tylo = pylo >> 3, tyhi = pyhi >> 3;
    for (int ty = tylo; ty <= tyhi; ty++) {
        // pixel-center y range of this tile row
        const float tylo_c = (2.0f * (ty * TILE)            + 1.0f - IS) * (1.0f / IS);
        const float tyhi_c = (2.0f * (ty * TILE + TILE - 1) + 1.0f - IS) * (1.0f / IS);
        const float y0t = fmaxf(nB0 * tylo_c, nB0 * tyhi_c);
        const float y1t = fmaxf(nB1 * tylo_c, nB1 * tyhi_c);
        const float y2t = fmaxf(nB2 * tylo_c, nB2 * tyhi_c);
        for (int tx = txlo; tx <= txhi; tx++) {
            const float txlo_c = (2.0f * (tx * TILE)            + 1.0f - IS) * (1.0f / IS);
            const float txhi_c = (2.0f * (tx * TILE + TILE - 1) + 1.0f - IS) * (1.0f / IS);
            // max of each normalized edge fn over the tile's pixel-center rect
            const float m0 = fmaxf(nA0 * txlo_c, nA0 * txhi_c) + y0t + nC0;
            const float m1 = fmaxf(nA1 * txlo_c, nA1 * txhi_c) + y1t + nC1;
            const float m2 = fmaxf(nA2 * txlo_c, nA2 * txhi_c) + y2t + nC2;
            if (m0 < m0e || m1 < m1e || m2 < m2e) continue;  // edge fully excludes tile
            const int bin = (b * NTX + ty) * NTX + tx;
            const int pos = atomicAdd(&g_binCnt[bin], 1);
            if (pos < BINCAP) g_binList[bin * BINCAP + pos] = f;
        }
    }
}

__device__ __forceinline__ void shade_pixel(
    const float* __restrict__ faces, const float* __restrict__ tex,
    float* __restrict__ out, int b, int px, int py, int bestF,
    float xp, float yp)
{
    float r = 0.f, g = 0.f, bl = 0.f, alpha = 0.f, depth = FAR_P;
    if (bestF >= 0) {
        const float* fv = faces + ((size_t)b * FACES + bestF) * 9;
        const float x0 = fv[0], y0 = fv[1], z0 = fv[2];
        const float x1 = fv[3], y1 = fv[4], z1 = fv[5];
        const float x2 = fv[6], y2 = fv[7], z2 = fv[8];

        const float w0 = yp * (x2 - x1) + xp * (y1 - y2) + (x1 * y2 - x2 * y1);
        const float w1 = yp * (x0 - x2) + xp * (y2 - y0) + (x2 * y0 - x0 * y2);
        const float w2 = yp * (x1 - x0) + xp * (y0 - y1) + (x0 * y1 - x1 * y0);
        float det = w0 + w1 + w2;
        if (!(fabsf(det) > TINYF)) det = 1.0f;
        float n0 = w0 / det, n1 = w1 / det, n2 = w2 / det;
        n0 = fminf(fmaxf(n0, 0.f), 1.f);
        n1 = fminf(fmaxf(n1, 0.f), 1.f);
        n2 = fminf(fmaxf(n2, 0.f), 1.f);
        float s = n0 + n1 + n2;
        if (!(s > TINYF)) s = 1.0f;
        n0 /= s; n1 /= s; n2 /= s;
        float invz = n0 / z0 + n1 / z1 + n2 / z2;
        if (!(fabsf(invz) > TINYF)) invz = 1.0f;
        const float zp = 1.0f / invz;
        depth = zp;
        alpha = 1.0f;

        const float hi = 3.0f - EPSV;   // T-1-EPS, T=4
        const float t0 = fminf(fmaxf(n0 * 3.0f * zp / z0, 0.f), hi);
        const float t1 = fminf(fmaxf(n1 * 3.0f * zp / z1, 0.f), hi);
        const float t2 = fminf(fmaxf(n2 * 3.0f * zp / z2, 0.f), hi);
        const float l0f = floorf(t0), l1f = floorf(t1), l2f = floorf(t2);
        const float f0 = t0 - l0f, f1 = t1 - l1f, f2 = t2 - l2f;
        const int l0 = (int)l0f, l1 = (int)l1f, l2 = (int)l2f;

        const float* tp = tex + ((size_t)b * FACES + bestF) * 192;
        #pragma unroll
        for (int d0 = 0; d0 < 2; d0++) {
            const float wx = d0 ? f0 : 1.0f - f0;
            #pragma unroll
            for (int d1 = 0; d1 < 2; d1++) {
                const float wy = wx * (d1 ? f1 : 1.0f - f1);
                #pragma unroll
                for (int d2 = 0; d2 < 2; d2++) {
                    const float wgt = wy * (d2 ? f2 : 1.0f - f2);
                    const int idx = ((l0 + d0) * 16 + (l1 + d1) * 4 + (l2 + d2)) * 3;
                    r  += wgt * tp[idx + 0];
                    g  += wgt * tp[idx + 1];
                    bl += wgt * tp[idx + 2];
                }
            }
        }
    }
    float* o = out + (((size_t)b * IS + py) * IS + px) * 5;
    o[0] = r; o[1] = g; o[2] = bl; o[3] = alpha; o[4] = depth;
}

// 8 warps per CTA, each warp owns one 8x8 tile; 2 pixels per lane.
// No __syncthreads anywhere — warps run fully independently.
__global__ __launch_bounds__(256) void raster_kernel(
    const float* __restrict__ faces,
    const float* __restrict__ tex,
    float* __restrict__ out)
{
    __shared__ float4 sc[8][32][3];
    __shared__ int    sidx[8][32];

    const int tid  = threadIdx.x;
    const int warp = tid >> 5;
    const int lane = tid & 31;
    const int b    = blockIdx.z;

    const int tilex = blockIdx.x * 4 + (warp & 3);
    const int tiley = blockIdx.y * 2 + (warp >> 2);

    const int px  = tilex * TILE + (lane & 7);
    const int py0 = tiley * TILE + (lane >> 3);        // rows 0..3
    const int py1 = py0 + 4;                           // rows 4..7

    const float xp  = (2.0f * px  + 1.0f - IS) * (1.0f / IS);
    const float yp0 = (2.0f * py0 + 1.0f - IS) * (1.0f / IS);
    const float yp1 = (2.0f * py1 + 1.0f - IS) * (1.0f / IS);

    const int bin = (b * NTX + tiley) * NTX + tilex;
    int n = 0;
    if (lane == 0) {
        n = min(g_binCnt[bin], BINCAP);
        g_binCnt[bin] = 0;                 // reset for the next graph replay
    }
    n = __shfl_sync(0xffffffffu, n, 0);

    float bi0 = 0.0f, bi1 = 0.0f;
    int   bf0 = -1,   bf1 = -1;

    for (int start = 0; start < n; start += 32) {
        const int cnt = min(32, n - start);
        if (lane < cnt) {
            const int f  = g_binList[bin * BINCAP + start + lane];
            const int id = b * FACES + f;
            sc[warp][lane][0] = g_c0[id];
            sc[warp][lane][1] = g_c1[id];
            sc[warp][lane][2] = g_c2[id];
            sidx[warp][lane]  = f;
        }
        __syncwarp();

        for (int c = 0; c < cnt; c++) {
            const float4 a0 = sc[warp][c][0];
            const float4 a1 = sc[warp][c][1];
            const float4 a2 = sc[warp][c][2];
            // pixel 0
            {
                const float n0 = fmaf(xp, a0.x, fmaf(yp0, a0.y, a0.z));
                const float n1 = fmaf(xp, a1.x, fmaf(yp0, a1.y, a1.z));
                const float n2 = fmaf(xp, a2.x, fmaf(yp0, a2.y, a2.z));
                const float iz = fmaf(xp, a0.w, fmaf(yp0, a1.w, a2.w));
                const float mn = fminf(n0, fminf(n1, n2));
                if (mn > 0.0f && iz > (1.0f / FAR_P) && iz < (1.0f / NEAR_P)) {
                    const int f = sidx[warp][c];
                    if (iz > bi0 || (iz == bi0 && f < bf0)) { bi0 = iz; bf0 = f; }
                }
            }
            // pixel 1 (same column, +4 rows)
            {
                const float n0 = fmaf(xp, a0.x, fmaf(yp1, a0.y, a0.z));
                const float n1 = fmaf(xp, a1.x, fmaf(yp1, a1.y, a1.z));
                const float n2 = fmaf(xp, a2.x, fmaf(yp1, a2.y, a2.z));
                const float iz = fmaf(xp, a0.w, fmaf(yp1, a1.w, a2.w));
                const float mn = fminf(n0, fminf(n1, n2));
                if (mn > 0.0f && iz > (1.0f / FAR_P) && iz < (1.0f / NEAR_P)) {
                    const int f = sidx[warp][c];
                    if (iz > bi1 || (iz == bi1 && f < bf1)) { bi1 = iz; bf1 = f; }
                }
            }
        }
        __syncwarp();
    }

    shade_pixel(faces, tex, out, b, px, py0, bf0, xp, yp0);
    shade_pixel(faces, tex, out, b, px, py1, bf1, xp, yp1);
}

extern "C" void kernel_launch(void* const* d_in, const int* in_sizes, int n_in,
                              void* d_out, int out_size)
{
    const float* faces = (const float*)d_in[0];
    const float* tex   = (const float*)d_in[1];
    float* out         = (float*)d_out;

    setup_kernel<<<(NBATCH * FACES) / 256, 256>>>(faces);
    dim3 grid(NTX / 4, NTX / 2, NBATCH);   // 8 x 16 x 4 CTAs, 8 tiles each
    raster_kernel<<<grid, 256>>>(faces, tex, out);
}

// round 7
// speedup vs baseline: 1.5207x; 1.2869x over previous
#include <cuda_runtime.h>

#define IS      256
#define TILE    8
#define NTX     (IS / TILE)      // 32 tiles per dim
#define FACES   4096
#define NBATCH  4
#define NEAR_P  0.1f
#define FAR_P   100.0f
#define TINYF   1e-12f
#define EPSV    0.001f
#define BINCAP  256
#define NBINS   (NBATCH * NTX * NTX)   // 4096
#define SLOTS   16                      // max 4x4 tiles per face bbox

// Per-face precomputed, normalized by det:
//   g_c0 = (nA0, nB0, nC0, P)
//   g_c1 = (nA1, nB1, nC1, Q)
//   g_c2 = (nA2, nB2, nC2, R)
// n_i(x,y) = nA_i*x + nB_i*y + nC_i   (== w_i/det)
// inv_zp(x,y) = P*x + Q*y + R
__device__ float4 g_c0[NBATCH * FACES];
__device__ float4 g_c1[NBATCH * FACES];
__device__ float4 g_c2[NBATCH * FACES];
__device__ int    g_binCnt[NBINS];          // zero-init at load; raster re-zeros
__device__ int    g_binList[NBINS * BINCAP];

// One thread per (face, tile-slot). Slot 0 also writes the normalized coeffs.
__global__ __launch_bounds__(256) void setup_kernel(const float* __restrict__ faces)
{
    const int gid  = blockIdx.x * 256 + threadIdx.x;   // 0 .. B*F*SLOTS-1
    const int id   = gid >> 4;                          // face id 0..B*F-1
    const int slot = gid & (SLOTS - 1);
    const int b = id >> 12;
    const int f = id & (FACES - 1);

    const float* fv = faces + (size_t)id * 9;
    const float x0 = fv[0], y0 = fv[1], z0 = fv[2];
    const float x1 = fv[3], y1 = fv[4], z1 = fv[5];
    const float x2 = fv[6], y2 = fv[7], z2 = fv[8];

    const float A0 = y1 - y2, B0 = x2 - x1, C0 = x1 * y2 - x2 * y1;
    const float A1 = y2 - y0, B1 = x0 - x2, C1 = x2 * y0 - x0 * y2;
    const float A2 = y0 - y1, B2 = x1 - x0, C2 = x0 * y1 - x1 * y0;
    const float det = C0 + C1 + C2;      // x/y coeffs cancel: det is constant
    if (!(fabsf(det) > TINYF)) return;   // degenerate: never inside, never binned

    if (slot == 0) {
        // only 1/16 of threads pay the MUFU cost
        const float rd  = 1.0f / det;
        const float rz0 = 1.0f / z0, rz1 = 1.0f / z1, rz2 = 1.0f / z2;
        const float nA0 = A0 * rd, nB0 = B0 * rd, nC0 = C0 * rd;
        const float nA1 = A1 * rd, nB1 = B1 * rd, nC1 = C1 * rd;
        const float nA2 = A2 * rd, nB2 = B2 * rd, nC2 = C2 * rd;
        g_c0[id] = make_float4(nA0, nB0, nC0, nA0 * rz0 + nA1 * rz1 + nA2 * rz2);
        g_c1[id] = make_float4(nA1, nB1, nC1, nB0 * rz0 + nB1 * rz1 + nB2 * rz2);
        g_c2[id] = make_float4(nA2, nB2, nC2, nC0 * rz0 + nC1 * rz1 + nC2 * rz2);
    }

    const float xmn = fminf(x0, fminf(x1, x2)), xmx = fmaxf(x0, fmaxf(x1, x2));
    const float ymn = fminf(y0, fminf(y1, y2)), ymx = fmaxf(y0, fmaxf(y1, y2));

    // pixel center xp = (2*px + 1 - IS)/IS  =>  px = (IS*xp + IS-1)/2 ; widen 1px
    int pxlo = (int)ceilf ((xmn * IS + (IS - 1)) * 0.5f) - 1;
    int pxhi = (int)floorf((xmx * IS + (IS - 1)) * 0.5f) + 1;
    int pylo = (int)ceilf ((ymn * IS + (IS - 1)) * 0.5f) - 1;
    int pyhi = (int)floorf((ymx * IS + (IS - 1)) * 0.5f) + 1;
    pxlo = max(pxlo, 0); pxhi = min(pxhi, IS - 1);
    pylo = max(pylo, 0); pyhi = min(pyhi, IS - 1);
    if (pxlo > pxhi || pylo > pyhi) return;

    const int txlo = pxlo >> 3, txhi = pxhi >> 3;
    const int tylo = pylo >> 3, tyhi = pyhi >> 3;
    const int nx = txhi - txlo + 1;
    const int ny = tyhi - tylo + 1;
    if (slot >= nx * ny) return;

    const int tx = txlo + (slot - (slot / nx) * nx);
    const int ty = tylo + slot / nx;

    // Conservative cull in UNNORMALIZED space (no division):
    // s*w_i = |det| * n_i ;  cull if max over tile rect of s*w_i < margin*|det|
    const float s = (det > 0.0f) ? 1.0f : -1.0f;
    const float sA0 = s * A0, sB0 = s * B0, sC0 = s * C0;
    const float sA1 = s * A1, sB1 = s * B1, sC1 = s * C1;
    const float sA2 = s * A2, sB2 = s * B2, sC2 = s * C2;

    const float txlo_c = (2.0f * (tx * TILE)            + 1.0f - IS) * (1.0f / IS);
    const float txhi_c = (2.0f * (tx * TILE + TILE - 1) + 1.0f - IS) * (1.0f / IS);
    const float tylo_c = (2.0f * (ty * TILE)            + 1.0f - IS) * (1.0f / IS);
    const float tyhi_c = (2.0f * (ty * TILE + TILE - 1) + 1.0f - IS) * (1.0f / IS);

    const float m0 = fmaxf(sA0 * txlo_c, sA0 * txhi_c) + fmaxf(sB0 * tylo_c, sB0 * tyhi_c) + sC0;
    const float m1 = fmaxf(sA1 * txlo_c, sA1 * txhi_c) + fmaxf(sB1 * tylo_c, sB1 * tyhi_c) + sC1;
    const float m2 = fmaxf(sA2 * txlo_c, sA2 * txhi_c) + fmaxf(sB2 * tylo_c, sB2 * tyhi_c) + sC2;

    const float ad  = fabsf(det);
    const float t0 = -1e-5f * (fabsf(A0) + fabsf(B0)) - 1e-6f * ad;
    const float t1 = -1e-5f * (fabsf(A1) + fabsf(B1)) - 1e-6f * ad;
    const float t2 = -1e-5f * (fabsf(A2) + fabsf(B2)) - 1e-6f * ad;
    if (m0 < t0 || m1 < t1 || m2 < t2) return;   // some edge fully excludes tile

    const int bin = (b * NTX + ty) * NTX + tx;
    const int pos = atomicAdd(&g_binCnt[bin], 1);
    if (pos < BINCAP) g_binList[bin * BINCAP + pos] = f;
}

__device__ __forceinline__ void shade_pixel(
    const float* __restrict__ faces, const float* __restrict__ tex,
    float* __restrict__ out, int b, int px, int py, int bestF,
    float xp, float yp)
{
    float r = 0.f, g = 0.f, bl = 0.f, alpha = 0.f, depth = FAR_P;
    if (bestF >= 0) {
        const float* fv = faces + ((size_t)b * FACES + bestF) * 9;
        const float x0 = fv[0], y0 = fv[1], z0 = fv[2];
        const float x1 = fv[3], y1 = fv[4], z1 = fv[5];
        const float x2 = fv[6], y2 = fv[7], z2 = fv[8];

        const float w0 = yp * (x2 - x1) + xp * (y1 - y2) + (x1 * y2 - x2 * y1);
        const float w1 = yp * (x0 - x2) + xp * (y2 - y0) + (x2 * y0 - x0 * y2);
        const float w2 = yp * (x1 - x0) + xp * (y0 - y1) + (x0 * y1 - x1 * y0);
        float det = w0 + w1 + w2;
        if (!(fabsf(det) > TINYF)) det = 1.0f;
        float n0 = w0 / det, n1 = w1 / det, n2 = w2 / det;
        n0 = fminf(fmaxf(n0, 0.f), 1.f);
        n1 = fminf(fmaxf(n1, 0.f), 1.f);
        n2 = fminf(fmaxf(n2, 0.f), 1.f);
        float s = n0 + n1 + n2;
        if (!(s > TINYF)) s = 1.0f;
        n0 /= s; n1 /= s; n2 /= s;
        float invz = n0 / z0 + n1 / z1 + n2 / z2;
        if (!(fabsf(invz) > TINYF)) invz = 1.0f;
        const float zp = 1.0f / invz;
        depth = zp;
        alpha = 1.0f;

        const float hi = 3.0f - EPSV;   // T-1-EPS, T=4
        const float t0 = fminf(fmaxf(n0 * 3.0f * zp / z0, 0.f), hi);
        const float t1 = fminf(fmaxf(n1 * 3.0f * zp / z1, 0.f), hi);
        const float t2 = fminf(fmaxf(n2 * 3.0f * zp / z2, 0.f), hi);
        const float l0f = floorf(t0), l1f = floorf(t1), l2f = floorf(t2);
        const float f0 = t0 - l0f, f1 = t1 - l1f, f2 = t2 - l2f;
        const int l0 = (int)l0f, l1 = (int)l1f, l2 = (int)l2f;

        const float* tp = tex + ((size_t)b * FACES + bestF) * 192;
        #pragma unroll
        for (int d0 = 0; d0 < 2; d0++) {
            const float wx = d0 ? f0 : 1.0f - f0;
            #pragma unroll
            for (int d1 = 0; d1 < 2; d1++) {
                const float wy = wx * (d1 ? f1 : 1.0f - f1);
                #pragma unroll
                for (int d2 = 0; d2 < 2; d2++) {
                    const float wgt = wy * (d2 ? f2 : 1.0f - f2);
                    const int idx = ((l0 + d0) * 16 + (l1 + d1) * 4 + (l2 + d2)) * 3;
                    r  += wgt * tp[idx + 0];
                    g  += wgt * tp[idx + 1];
                    bl += wgt * tp[idx + 2];
                }
            }
        }
    }
    float* o = out + (((size_t)b * IS + py) * IS + px) * 5;
    o[0] = r; o[1] = g; o[2] = bl; o[3] = alpha; o[4] = depth;
}

// 8 warps per CTA, each warp owns one 8x8 tile; 2 pixels per lane.
// No __syncthreads anywhere — warps run fully independently.
__global__ __launch_bounds__(256) void raster_kernel(
    const float* __restrict__ faces,
    const float* __restrict__ tex,
    float* __restrict__ out)
{
    __shared__ float4 sc[8][32][3];
    __shared__ int    sidx[8][32];

    const int tid  = threadIdx.x;
    const int warp = tid >> 5;
    const int lane = tid & 31;
    const int b    = blockIdx.z;

    const int tilex = blockIdx.x * 4 + (warp & 3);
    const int tiley = blockIdx.y * 2 + (warp >> 2);

    const int px  = tilex * TILE + (lane & 7);
    const int py0 = tiley * TILE + (lane >> 3);        // rows 0..3
    const int py1 = py0 + 4;                           // rows 4..7

    const float xp  = (2.0f * px  + 1.0f - IS) * (1.0f / IS);
    const float yp0 = (2.0f * py0 + 1.0f - IS) * (1.0f / IS);
    const float yp1 = (2.0f * py1 + 1.0f - IS) * (1.0f / IS);

    const int bin = (b * NTX + tiley) * NTX + tilex;
    int n = 0;
    if (lane == 0) {
        n = min(g_binCnt[bin], BINCAP);
        g_binCnt[bin] = 0;                 // reset for the next graph replay
    }
    n = __shfl_sync(0xffffffffu, n, 0);

    float bi0 = 0.0f, bi1 = 0.0f;
    int   bf0 = -1,   bf1 = -1;

    for (int start = 0; start < n; start += 32) {
        const int cnt = min(32, n - start);
        if (lane < cnt) {
            const int f  = g_binList[bin * BINCAP + start + lane];
            const int id = b * FACES + f;
            sc[warp][lane][0] = g_c0[id];
            sc[warp][lane][1] = g_c1[id];
            sc[warp][lane][2] = g_c2[id];
            sidx[warp][lane]  = f;
        }
        __syncwarp();

        for (int c = 0; c < cnt; c++) {
            const float4 a0 = sc[warp][c][0];
            const float4 a1 = sc[warp][c][1];
            const float4 a2 = sc[warp][c][2];
            // pixel 0
            {
                const float n0 = fmaf(xp, a0.x, fmaf(yp0, a0.y, a0.z));
                const float n1 = fmaf(xp, a1.x, fmaf(yp0, a1.y, a1.z));
                const float n2 = fmaf(xp, a2.x, fmaf(yp0, a2.y, a2.z));
                const float iz = fmaf(xp, a0.w, fmaf(yp0, a1.w, a2.w));
                const float mn = fminf(n0, fminf(n1, n2));
                if (mn > 0.0f && iz > (1.0f / FAR_P) && iz < (1.0f / NEAR_P)) {
                    const int f = sidx[warp][c];
                    if (iz > bi0 || (iz == bi0 && f < bf0)) { bi0 = iz; bf0 = f; }
                }
            }
            // pixel 1 (same column, +4 rows)
            {
                const float n0 = fmaf(xp, a0.x, fmaf(yp1, a0.y, a0.z));
                const float n1 = fmaf(xp, a1.x, fmaf(yp1, a1.y, a1.z));
                const float n2 = fmaf(xp, a2.x, fmaf(yp1, a2.y, a2.z));
                const float iz = fmaf(xp, a0.w, fmaf(yp1, a1.w, a2.w));
                const float mn = fminf(n0, fminf(n1, n2));
                if (mn > 0.0f && iz > (1.0f / FAR_P) && iz < (1.0f / NEAR_P)) {
                    const int f = sidx[warp][c];
                    if (iz > bi1 || (iz == bi1 && f < bf1)) { bi1 = iz; bf1 = f; }
                }
            }
        }
        __syncwarp();
    }

    shade_pixel(faces, tex, out, b, px, py0, bf0, xp, yp0);
    shade_pixel(faces, tex, out, b, px, py1, bf1, xp, yp1);
}

extern "C" void kernel_launch(void* const* d_in, const int* in_sizes, int n_in,
                              void* d_out, int out_size)
{
    const float* faces = (const float*)d_in[0];
    const float* tex   = (const float*)d_in[1];
    float* out         = (float*)d_out;

    setup_kernel<<<(NBATCH * FACES * SLOTS) / 256, 256>>>(faces);
    dim3 grid(NTX / 4, NTX / 2, NBATCH);   // 8 x 16 x 4 CTAs, 8 tiles each
    raster_kernel<<<grid, 256>>>(faces, tex, out);
}

// round 8
// speedup vs baseline: 1.7889x; 1.1764x over previous
#include <cuda_runtime.h>

#define IS      256
#define TILE    8
#define NTX     (IS / TILE)      // 32 tiles per dim
#define FACES   4096
#define NBATCH  4
#define NEAR_P  0.1f
#define FAR_P   100.0f
#define TINYF   1e-12f
#define EPSV    0.001f
#define BINCAP  256
#define NBINS   (NBATCH * NTX * NTX)   // 4096
#define SLOTS   16                      // max 4x4 tiles per face bbox

// Per-face precomputed, normalized by det:
//   g_c0 = (nA0, nB0, nC0, P)
//   g_c1 = (nA1, nB1, nC1, Q)
//   g_c2 = (nA2, nB2, nC2, R)
// n_i(x,y) = nA_i*x + nB_i*y + nC_i   (== w_i/det)
// inv_zp(x,y) = P*x + Q*y + R
__device__ float4 g_c0[NBATCH * FACES];
__device__ float4 g_c1[NBATCH * FACES];
__device__ float4 g_c2[NBATCH * FACES];
__device__ int    g_binCnt[NBINS];          // zero-init at load; raster re-zeros
__device__ int    g_binList[NBINS * BINCAP];

// One thread per (face, tile-slot). Slot 0 also writes the normalized coeffs.
__global__ __launch_bounds__(256) void setup_kernel(const float* __restrict__ faces)
{
    const int gid  = blockIdx.x * 256 + threadIdx.x;   // 0 .. B*F*SLOTS-1
    const int id   = gid >> 4;                          // face id 0..B*F-1
    const int slot = gid & (SLOTS - 1);
    const int b = id >> 12;
    const int f = id & (FACES - 1);

    const float* fv = faces + (size_t)id * 9;
    const float x0 = fv[0], y0 = fv[1], z0 = fv[2];
    const float x1 = fv[3], y1 = fv[4], z1 = fv[5];
    const float x2 = fv[6], y2 = fv[7], z2 = fv[8];

    const float A0 = y1 - y2, B0 = x2 - x1, C0 = x1 * y2 - x2 * y1;
    const float A1 = y2 - y0, B1 = x0 - x2, C1 = x2 * y0 - x0 * y2;
    const float A2 = y0 - y1, B2 = x1 - x0, C2 = x0 * y1 - x1 * y0;
    const float det = C0 + C1 + C2;      // x/y coeffs cancel: det is constant
    if (!(fabsf(det) > TINYF)) return;   // degenerate: never inside, never binned

    if (slot == 0) {
        // only 1/16 of threads pay the MUFU cost
        const float rd  = 1.0f / det;
        const float rz0 = 1.0f / z0, rz1 = 1.0f / z1, rz2 = 1.0f / z2;
        const float nA0 = A0 * rd, nB0 = B0 * rd, nC0 = C0 * rd;
        const float nA1 = A1 * rd, nB1 = B1 * rd, nC1 = C1 * rd;
        const float nA2 = A2 * rd, nB2 = B2 * rd, nC2 = C2 * rd;
        g_c0[id] = make_float4(nA0, nB0, nC0, nA0 * rz0 + nA1 * rz1 + nA2 * rz2);
        g_c1[id] = make_float4(nA1, nB1, nC1, nB0 * rz0 + nB1 * rz1 + nB2 * rz2);
        g_c2[id] = make_float4(nA2, nB2, nC2, nC0 * rz0 + nC1 * rz1 + nC2 * rz2);
    }

    const float xmn = fminf(x0, fminf(x1, x2)), xmx = fmaxf(x0, fmaxf(x1, x2));
    const float ymn = fminf(y0, fminf(y1, y2)), ymx = fmaxf(y0, fmaxf(y1, y2));

    // pixel center xp = (2*px + 1 - IS)/IS  =>  px = (IS*xp + IS-1)/2 ; widen 1px
    int pxlo = (int)ceilf ((xmn * IS + (IS - 1)) * 0.5f) - 1;
    int pxhi = (int)floorf((xmx * IS + (IS - 1)) * 0.5f) + 1;
    int pylo = (int)ceilf ((ymn * IS + (IS - 1)) * 0.5f) - 1;
    int pyhi = (int)floorf((ymx * IS + (IS - 1)) * 0.5f) + 1;
    pxlo = max(pxlo, 0); pxhi = min(pxhi, IS - 1);
    pylo = max(pylo, 0); pyhi = min(pyhi, IS - 1);
    if (pxlo > pxhi || pylo > pyhi) return;

    const int txlo = pxlo >> 3, txhi = pxhi >> 3;
    const int tylo = pylo >> 3, tyhi = pyhi >> 3;
    const int nx = txhi - txlo + 1;
    const int ny = tyhi - tylo + 1;
    if (slot >= nx * ny) return;

    const int tx = txlo + (slot - (slot / nx) * nx);
    const int ty = tylo + slot / nx;

    // Conservative cull in UNNORMALIZED space (no division):
    // s*w_i = |det| * n_i ;  cull if max over tile rect of s*w_i < margin*|det|
    const float s = (det > 0.0f) ? 1.0f : -1.0f;
    const float sA0 = s * A0, sB0 = s * B0, sC0 = s * C0;
    const float sA1 = s * A1, sB1 = s * B1, sC1 = s * C1;
    const float sA2 = s * A2, sB2 = s * B2, sC2 = s * C2;

    const float txlo_c = (2.0f * (tx * TILE)            + 1.0f - IS) * (1.0f / IS);
    const float txhi_c = (2.0f * (tx * TILE + TILE - 1) + 1.0f - IS) * (1.0f / IS);
    const float tylo_c = (2.0f * (ty * TILE)            + 1.0f - IS) * (1.0f / IS);
    const float tyhi_c = (2.0f * (ty * TILE + TILE - 1) + 1.0f - IS) * (1.0f / IS);

    const float m0 = fmaxf(sA0 * txlo_c, sA0 * txhi_c) + fmaxf(sB0 * tylo_c, sB0 * tyhi_c) + sC0;
    const float m1 = fmaxf(sA1 * txlo_c, sA1 * txhi_c) + fmaxf(sB1 * tylo_c, sB1 * tyhi_c) + sC1;
    const float m2 = fmaxf(sA2 * txlo_c, sA2 * txhi_c) + fmaxf(sB2 * tylo_c, sB2 * tyhi_c) + sC2;

    const float ad  = fabsf(det);
    const float t0 = -1e-5f * (fabsf(A0) + fabsf(B0)) - 1e-6f * ad;
    const float t1 = -1e-5f * (fabsf(A1) + fabsf(B1)) - 1e-6f * ad;
    const float t2 = -1e-5f * (fabsf(A2) + fabsf(B2)) - 1e-6f * ad;
    if (m0 < t0 || m1 < t1 || m2 < t2) return;   // some edge fully excludes tile

    const int bin = (b * NTX + ty) * NTX + tx;
    const int pos = atomicAdd(&g_binCnt[bin], 1);
    if (pos < BINCAP) g_binList[bin * BINCAP + pos] = f;
}

__device__ __forceinline__ void shade_pixel(
    const float* __restrict__ faces, const float* __restrict__ tex,
    float* __restrict__ out, int b, int px, int py, int bestF,
    float xp, float yp)
{
    float r = 0.f, g = 0.f, bl = 0.f, alpha = 0.f, depth = FAR_P;
    if (bestF >= 0) {
        const float* fv = faces + ((size_t)b * FACES + bestF) * 9;
        const float x0 = fv[0], y0 = fv[1], z0 = fv[2];
        const float x1 = fv[3], y1 = fv[4], z1 = fv[5];
        const float x2 = fv[6], y2 = fv[7], z2 = fv[8];

        const float w0 = yp * (x2 - x1) + xp * (y1 - y2) + (x1 * y2 - x2 * y1);
        const float w1 = yp * (x0 - x2) + xp * (y2 - y0) + (x2 * y0 - x0 * y2);
        const float w2 = yp * (x1 - x0) + xp * (y0 - y1) + (x0 * y1 - x1 * y0);
        float det = w0 + w1 + w2;
        if (!(fabsf(det) > TINYF)) det = 1.0f;
        float n0 = w0 / det, n1 = w1 / det, n2 = w2 / det;
        n0 = fminf(fmaxf(n0, 0.f), 1.f);
        n1 = fminf(fmaxf(n1, 0.f), 1.f);
        n2 = fminf(fmaxf(n2, 0.f), 1.f);
        float s = n0 + n1 + n2;
        if (!(s > TINYF)) s = 1.0f;
        n0 /= s; n1 /= s; n2 /= s;
        float invz = n0 / z0 + n1 / z1 + n2 / z2;
        if (!(fabsf(invz) > TINYF)) invz = 1.0f;
        const float zp = 1.0f / invz;
        depth = zp;
        alpha = 1.0f;

        const float hi = 3.0f - EPSV;   // T-1-EPS, T=4
        const float t0 = fminf(fmaxf(n0 * 3.0f * zp / z0, 0.f), hi);
        const float t1 = fminf(fmaxf(n1 * 3.0f * zp / z1, 0.f), hi);
        const float t2 = fminf(fmaxf(n2 * 3.0f * zp / z2, 0.f), hi);
        const float l0f = floorf(t0), l1f = floorf(t1), l2f = floorf(t2);
        const float f0 = t0 - l0f, f1 = t1 - l1f, f2 = t2 - l2f;
        const int l0 = (int)l0f, l1 = (int)l1f, l2 = (int)l2f;

        const float* tp = tex + ((size_t)b * FACES + bestF) * 192;
        #pragma unroll
        for (int d0 = 0; d0 < 2; d0++) {
            const float wx = d0 ? f0 : 1.0f - f0;
            #pragma unroll
            for (int d1 = 0; d1 < 2; d1++) {
                const float wy = wx * (d1 ? f1 : 1.0f - f1);
                #pragma unroll
                for (int d2 = 0; d2 < 2; d2++) {
                    const float wgt = wy * (d2 ? f2 : 1.0f - f2);
                    const int idx = ((l0 + d0) * 16 + (l1 + d1) * 4 + (l2 + d2)) * 3;
                    r  += wgt * tp[idx + 0];
                    g  += wgt * tp[idx + 1];
                    bl += wgt * tp[idx + 2];
                }
            }
        }
    }
    float* o = out + (((size_t)b * IS + py) * IS + px) * 5;
    o[0] = r; o[1] = g; o[2] = bl; o[3] = alpha; o[4] = depth;
}

// 8 warps per CTA. Each warp owns one 8x4 HALF-tile; 1 pixel per lane.
// CTA covers 4 tiles x 2 halves = 32x8 pixels. Only one __syncthreads
// (to order the bin-count reset after both half-warps read it).
__global__ __launch_bounds__(256) void raster_kernel(
    const float* __restrict__ faces,
    const float* __restrict__ tex,
    float* __restrict__ out)
{
    __shared__ float4 sc[8][32][3];
    __shared__ int    sidx[8][32];

    const int tid  = threadIdx.x;
    const int warp = tid >> 5;
    const int lane = tid & 31;
    const int b    = blockIdx.z;

    const int tilex = blockIdx.x * 4 + (warp & 3);
    const int tiley = blockIdx.y;
    const int half  = warp >> 2;                       // 0: rows 0-3, 1: rows 4-7

    const int px = tilex * TILE + (lane & 7);
    const int py = tiley * TILE + half * 4 + (lane >> 3);

    const float xp = (2.0f * px + 1.0f - IS) * (1.0f / IS);
    const float yp = (2.0f * py + 1.0f - IS) * (1.0f / IS);

    const int bin = (b * NTX + tiley) * NTX + tilex;
    int n = 0;
    if (lane == 0) n = min(g_binCnt[bin], BINCAP);
    n = __shfl_sync(0xffffffffu, n, 0);
    __syncthreads();                                   // both halves have read the count
    if (half == 0 && lane == 0) g_binCnt[bin] = 0;     // reset for next graph replay

    float bi = 0.0f;
    int   bf = -1;

    for (int start = 0; start < n; start += 32) {
        const int cnt = min(32, n - start);
        if (lane < cnt) {
            const int f  = g_binList[bin * BINCAP + start + lane];
            const int id = b * FACES + f;
            sc[warp][lane][0] = g_c0[id];
            sc[warp][lane][1] = g_c1[id];
            sc[warp][lane][2] = g_c2[id];
            sidx[warp][lane]  = f;
        }
        __syncwarp();

        for (int c = 0; c < cnt; c++) {
            const float4 a0 = sc[warp][c][0];
            const float4 a1 = sc[warp][c][1];
            const float4 a2 = sc[warp][c][2];
            const float n0 = fmaf(xp, a0.x, fmaf(yp, a0.y, a0.z));
            const float n1 = fmaf(xp, a1.x, fmaf(yp, a1.y, a1.z));
            const float n2 = fmaf(xp, a2.x, fmaf(yp, a2.y, a2.z));
            const float iz = fmaf(xp, a0.w, fmaf(yp, a1.w, a2.w));
            const float mn = fminf(n0, fminf(n1, n2));
            if (mn > 0.0f && iz > (1.0f / FAR_P) && iz < (1.0f / NEAR_P)) {
                const int f = sidx[warp][c];
                if (iz > bi || (iz == bi && f < bf)) { bi = iz; bf = f; }
            }
        }
        __syncwarp();
    }

    shade_pixel(faces, tex, out, b, px, py, bf, xp, yp);
}

extern "C" void kernel_launch(void* const* d_in, const int* in_sizes, int n_in,
                              void* d_out, int out_size)
{
    const float* faces = (const float*)d_in[0];
    const float* tex   = (const float*)d_in[1];
    float* out         = (float*)d_out;

    setup_kernel<<<(NBATCH * FACES * SLOTS) / 256, 256>>>(faces);
    dim3 grid(NTX / 4, NTX, NBATCH);   // 8 x 32 x 4 = 1024 CTAs, 8 half-tiles each
    raster_kernel<<<grid, 256>>>(faces, tex, out);
}

// round 9
// speedup vs baseline: 1.9634x; 1.0976x over previous
#include <cuda_runtime.h>

#define IS      256
#define TILE    8
#define NTX     (IS / TILE)      // 32 tiles per dim
#define FACES   4096
#define NBATCH  4
#define NEAR_P  0.1f
#define FAR_P   100.0f
#define TINYF   1e-12f
#define EPSV    0.001f
#define BINCAP  256
#define NBINS   (NBATCH * NTX * NTX)   // 4096
#define SLOTS   16                      // max 4x4 tiles per face bbox

// Per-face precomputed, normalized by det:
//   g_c0 = (nA0, nB0, nC0, P)
//   g_c1 = (nA1, nB1, nC1, Q)
//   g_c2 = (nA2, nB2, nC2, R)
//   g_rz = (1/z0, 1/z1, 1/z2, 0)
// n_i(x,y) = nA_i*x + nB_i*y + nC_i   (== w_i/det)
// inv_zp(x,y) = P*x + Q*y + R
__device__ float4 g_c0[NBATCH * FACES];
__device__ float4 g_c1[NBATCH * FACES];
__device__ float4 g_c2[NBATCH * FACES];
__device__ float4 g_rz[NBATCH * FACES];
__device__ int    g_binCnt[NBINS];          // zero-init at load; raster re-zeros
__device__ int    g_binList[NBINS * BINCAP];

// One thread per (face, tile-slot). Slot 0 also writes the normalized coeffs.
__global__ __launch_bounds__(256) void setup_kernel(const float* __restrict__ faces)
{
    const int gid  = blockIdx.x * 256 + threadIdx.x;   // 0 .. B*F*SLOTS-1
    const int id   = gid >> 4;                          // face id 0..B*F-1
    const int slot = gid & (SLOTS - 1);
    const int b = id >> 12;
    const int f = id & (FACES - 1);

    const float* fv = faces + (size_t)id * 9;
    const float x0 = fv[0], y0 = fv[1], z0 = fv[2];
    const float x1 = fv[3], y1 = fv[4], z1 = fv[5];
    const float x2 = fv[6], y2 = fv[7], z2 = fv[8];

    const float A0 = y1 - y2, B0 = x2 - x1, C0 = x1 * y2 - x2 * y1;
    const float A1 = y2 - y0, B1 = x0 - x2, C1 = x2 * y0 - x0 * y2;
    const float A2 = y0 - y1, B2 = x1 - x0, C2 = x0 * y1 - x1 * y0;
    const float det = C0 + C1 + C2;      // x/y coeffs cancel: det is constant
    if (!(fabsf(det) > TINYF)) return;   // degenerate: never inside, never binned

    if (slot == 0) {
        // only 1/16 of threads pay the MUFU cost
        const float rd  = 1.0f / det;
        const float rz0 = 1.0f / z0, rz1 = 1.0f / z1, rz2 = 1.0f / z2;
        const float nA0 = A0 * rd, nB0 = B0 * rd, nC0 = C0 * rd;
        const float nA1 = A1 * rd, nB1 = B1 * rd, nC1 = C1 * rd;
        const float nA2 = A2 * rd, nB2 = B2 * rd, nC2 = C2 * rd;
        g_c0[id] = make_float4(nA0, nB0, nC0, nA0 * rz0 + nA1 * rz1 + nA2 * rz2);
        g_c1[id] = make_float4(nA1, nB1, nC1, nB0 * rz0 + nB1 * rz1 + nB2 * rz2);
        g_c2[id] = make_float4(nA2, nB2, nC2, nC0 * rz0 + nC1 * rz1 + nC2 * rz2);
        g_rz[id] = make_float4(rz0, rz1, rz2, 0.0f);
    }

    const float xmn = fminf(x0, fminf(x1, x2)), xmx = fmaxf(x0, fmaxf(x1, x2));
    const float ymn = fminf(y0, fminf(y1, y2)), ymx = fmaxf(y0, fmaxf(y1, y2));

    // pixel center xp = (2*px + 1 - IS)/IS  =>  px = (IS*xp + IS-1)/2 ; widen 1px
    int pxlo = (int)ceilf ((xmn * IS + (IS - 1)) * 0.5f) - 1;
    int pxhi = (int)floorf((xmx * IS + (IS - 1)) * 0.5f) + 1;
    int pylo = (int)ceilf ((ymn * IS + (IS - 1)) * 0.5f) - 1;
    int pyhi = (int)floorf((ymx * IS + (IS - 1)) * 0.5f) + 1;
    pxlo = max(pxlo, 0); pxhi = min(pxhi, IS - 1);
    pylo = max(pylo, 0); pyhi = min(pyhi, IS - 1);
    if (pxlo > pxhi || pylo > pyhi) return;

    const int txlo = pxlo >> 3, txhi = pxhi >> 3;
    const int tylo = pylo >> 3, tyhi = pyhi >> 3;
    const int nx = txhi - txlo + 1;
    const int ny = tyhi - tylo + 1;
    if (slot >= nx * ny) return;

    const int tx = txlo + (slot - (slot / nx) * nx);
    const int ty = tylo + slot / nx;

    // Conservative cull in UNNORMALIZED space (no division):
    const float s = (det > 0.0f) ? 1.0f : -1.0f;
    const float sA0 = s * A0, sB0 = s * B0, sC0 = s * C0;
    const float sA1 = s * A1, sB1 = s * B1, sC1 = s * C1;
    const float sA2 = s * A2, sB2 = s * B2, sC2 = s * C2;

    const float txlo_c = (2.0f * (tx * TILE)            + 1.0f - IS) * (1.0f / IS);
    const float txhi_c = (2.0f * (tx * TILE + TILE - 1) + 1.0f - IS) * (1.0f / IS);
    const float tylo_c = (2.0f * (ty * TILE)            + 1.0f - IS) * (1.0f / IS);
    const float tyhi_c = (2.0f * (ty * TILE + TILE - 1) + 1.0f - IS) * (1.0f / IS);

    const float m0 = fmaxf(sA0 * txlo_c, sA0 * txhi_c) + fmaxf(sB0 * tylo_c, sB0 * tyhi_c) + sC0;
    const float m1 = fmaxf(sA1 * txlo_c, sA1 * txhi_c) + fmaxf(sB1 * tylo_c, sB1 * tyhi_c) + sC1;
    const float m2 = fmaxf(sA2 * txlo_c, sA2 * txhi_c) + fmaxf(sB2 * tylo_c, sB2 * tyhi_c) + sC2;

    const float ad  = fabsf(det);
    const float t0 = -1e-5f * (fabsf(A0) + fabsf(B0)) - 1e-6f * ad;
    const float t1 = -1e-5f * (fabsf(A1) + fabsf(B1)) - 1e-6f * ad;
    const float t2 = -1e-5f * (fabsf(A2) + fabsf(B2)) - 1e-6f * ad;
    if (m0 < t0 || m1 < t1 || m2 < t2) return;   // some edge fully excludes tile

    const int bin = (b * NTX + ty) * NTX + tx;
    const int pos = atomicAdd(&g_binCnt[bin], 1);
    if (pos < BINCAP) g_binList[bin * BINCAP + pos] = f;
}

// 8 warps per CTA. Each warp owns one 8x4 HALF-tile; 1 pixel per lane.
__global__ __launch_bounds__(256) void raster_kernel(
    const float* __restrict__ tex,
    float* __restrict__ out)
{
    __shared__ float4 sc[8][32][3];
    __shared__ int    sidx[8][32];

    const int tid  = threadIdx.x;
    const int warp = tid >> 5;
    const int lane = tid & 31;
    const int b    = blockIdx.z;

    const int tilex = blockIdx.x * 4 + (warp & 3);
    const int tiley = blockIdx.y;
    const int half  = warp >> 2;                       // 0: rows 0-3, 1: rows 4-7

    const int px = tilex * TILE + (lane & 7);
    const int py = tiley * TILE + half * 4 + (lane >> 3);

    const float xp = (2.0f * px + 1.0f - IS) * (1.0f / IS);
    const float yp = (2.0f * py + 1.0f - IS) * (1.0f / IS);

    const int bin = (b * NTX + tiley) * NTX + tilex;
    int n = 0;
    if (lane == 0) n = min(g_binCnt[bin], BINCAP);
    n = __shfl_sync(0xffffffffu, n, 0);
    __syncthreads();                                   // both halves have read the count
    if (half == 0 && lane == 0) g_binCnt[bin] = 0;     // reset for next graph replay

    // Two independent accumulators (merged at the end) for ILP.
    // Init to 1/FAR: "iz > bi" then subsumes the far-clip test.
    float biA = 1.0f / FAR_P, biB = 1.0f / FAR_P;
    int   bfA = -1,           bfB = -1;

    for (int start = 0; start < n; start += 32) {
        const int cnt = min(32, n - start);
        if (lane < cnt) {
            const int f  = g_binList[bin * BINCAP + start + lane];
            const int id = b * FACES + f;
            sc[warp][lane][0] = g_c0[id];
            sc[warp][lane][1] = g_c1[id];
            sc[warp][lane][2] = g_c2[id];
            sidx[warp][lane]  = f;
        }
        __syncwarp();

        int c = 0;
        for (; c + 1 < cnt; c += 2) {
            // candidate c -> accumulator A
            {
                const float4 a0 = sc[warp][c][0];
                const float4 a1 = sc[warp][c][1];
                const float4 a2 = sc[warp][c][2];
                const float n0 = fmaf(xp, a0.x, fmaf(yp, a0.y, a0.z));
                const float n1 = fmaf(xp, a1.x, fmaf(yp, a1.y, a1.z));
                const float n2 = fmaf(xp, a2.x, fmaf(yp, a2.y, a2.z));
                const float iz = fmaf(xp, a0.w, fmaf(yp, a1.w, a2.w));
                const float mn = fminf(n0, fminf(n1, n2));
                const int f = sidx[warp][c];
                if (mn > 0.0f && iz < (1.0f / NEAR_P) &&
                    (iz > biA || (iz == biA && f < bfA))) { biA = iz; bfA = f; }
            }
            // candidate c+1 -> accumulator B
            {
                const float4 a0 = sc[warp][c + 1][0];
                const float4 a1 = sc[warp][c + 1][1];
                const float4 a2 = sc[warp][c + 1][2];
                const float n0 = fmaf(xp, a0.x, fmaf(yp, a0.y, a0.z));
                const float n1 = fmaf(xp, a1.x, fmaf(yp, a1.y, a1.z));
                const float n2 = fmaf(xp, a2.x, fmaf(yp, a2.y, a2.z));
                const float iz = fmaf(xp, a0.w, fmaf(yp, a1.w, a2.w));
                const float mn = fminf(n0, fminf(n1, n2));
                const int f = sidx[warp][c + 1];
                if (mn > 0.0f && iz < (1.0f / NEAR_P) &&
                    (iz > biB || (iz == biB && f < bfB))) { biB = iz; bfB = f; }
            }
        }
        if (c < cnt) {
            const float4 a0 = sc[warp][c][0];
            const float4 a1 = sc[warp][c][1];
            const float4 a2 = sc[warp][c][2];
            const float n0 = fmaf(xp, a0.x, fmaf(yp, a0.y, a0.z));
            const float n1 = fmaf(xp, a1.x, fmaf(yp, a1.y, a1.z));
            const float n2 = fmaf(xp, a2.x, fmaf(yp, a2.y, a2.z));
            const float iz = fmaf(xp, a0.w, fmaf(yp, a1.w, a2.w));
            const float mn = fminf(n0, fminf(n1, n2));
            const int f = sidx[warp][c];
            if (mn > 0.0f && iz < (1.0f / NEAR_P) &&
                (iz > biA || (iz == biA && f < bfA))) { biA = iz; bfA = f; }
        }
        __syncwarp();
    }

    // merge accumulators (order-independent rule: max iz, tie -> min face)
    if (biB > biA || (biB == biA && (unsigned)bfB < (unsigned)bfA)) {
        biA = biB; bfA = bfB;
    }
    const int bestF = bfA;

    // -------- shading from precomputed coefficients --------
    float r = 0.f, g = 0.f, bl = 0.f, alpha = 0.f, depth = FAR_P;
    if (bestF >= 0) {
        const int idw = b * FACES + bestF;
        const float4 a0 = g_c0[idw];
        const float4 a1 = g_c1[idw];
        const float4 a2 = g_c2[idw];
        const float4 rz = g_rz[idw];

        float n0 = fmaf(xp, a0.x, fmaf(yp, a0.y, a0.z));
        float n1 = fmaf(xp, a1.x, fmaf(yp, a1.y, a1.z));
        float n2 = fmaf(xp, a2.x, fmaf(yp, a2.y, a2.z));
        n0 = fminf(fmaxf(n0, 0.f), 1.f);
        n1 = fminf(fmaxf(n1, 0.f), 1.f);
        n2 = fminf(fmaxf(n2, 0.f), 1.f);
        float s = n0 + n1 + n2;
        if (!(s > TINYF)) s = 1.0f;
        const float rs = 1.0f / s;
        const float u0 = n0 * rs * rz.x;
        const float u1 = n1 * rs * rz.y;
        const float u2 = n2 * rs * rz.z;
        float invz = u0 + u1 + u2;
        if (!(fabsf(invz) > TINYF)) invz = 1.0f;
        const float zp = 1.0f / invz;
        depth = zp;
        alpha = 1.0f;

        const float hi = 3.0f - EPSV;   // T-1-EPS, T=4
        const float zp3 = 3.0f * zp;
        const float t0 = fminf(fmaxf(u0 * zp3, 0.f), hi);
        const float t1 = fminf(fmaxf(u1 * zp3, 0.f), hi);
        const float t2 = fminf(fmaxf(u2 * zp3, 0.f), hi);
        const float l0f = floorf(t0), l1f = floorf(t1), l2f = floorf(t2);
        const float f0 = t0 - l0f, f1 = t1 - l1f, f2 = t2 - l2f;
        const int l0 = (int)l0f, l1 = (int)l1f, l2 = (int)l2f;

        const float* tp = tex + (size_t)idw * 192;
        #pragma unroll
        for (int d0 = 0; d0 < 2; d0++) {
            const float wx = d0 ? f0 : 1.0f - f0;
            #pragma unroll
            for (int d1 = 0; d1 < 2; d1++) {
                const float wy = wx * (d1 ? f1 : 1.0f - f1);
                #pragma unroll
                for (int d2 = 0; d2 < 2; d2++) {
                    const float wgt = wy * (d2 ? f2 : 1.0f - f2);
                    const int idx = ((l0 + d0) * 16 + (l1 + d1) * 4 + (l2 + d2)) * 3;
                    r  += wgt * tp[idx + 0];
                    g  += wgt * tp[idx + 1];
                    bl += wgt * tp[idx + 2];
                }
            }
        }
    }
    float* o = out + (((size_t)b * IS + py) * IS + px) * 5;
    o[0] = r; o[1] = g; o[2] = bl; o[3] = alpha; o[4] = depth;
}

extern "C" void kernel_launch(void* const* d_in, const int* in_sizes, int n_in,
                              void* d_out, int out_size)
{
    const float* faces = (const float*)d_in[0];
    const float* tex   = (const float*)d_in[1];
    float* out         = (float*)d_out;

    setup_kernel<<<(NBATCH * FACES * SLOTS) / 256, 256>>>(faces);
    dim3 grid(NTX / 4, NTX, NBATCH);   // 8 x 32 x 4 = 1024 CTAs, 8 half-tiles each
    raster_kernel<<<grid, 256>>>(tex, out);
}

// round 10
// speedup vs baseline: 1.9664x; 1.0015x over previous
#include <cuda_runtime.h>

#define IS      256
#define TILE    8
#define NTX     (IS / TILE)      // 32 tiles per dim
#define FACES   4096
#define NBATCH  4
#define NEAR_P  0.1f
#define FAR_P   100.0f
#define TINYF   1e-12f
#define EPSV    0.001f
#define BINCAP  256
#define NBINS   (NBATCH * NTX * NTX)   // 4096
#define SLOTS   16                      // max 4x4 tiles per face bbox

typedef unsigned long long u64;

// Per-face precomputed, normalized by det:
//   g_c0 = (nA0, nB0, nC0, P)
//   g_c1 = (nA1, nB1, nC1, Q)
//   g_c2 = (nA2, nB2, nC2, R)
//   g_rz = (1/z0, 1/z1, 1/z2, 0)
// n_i(x,y) = nA_i*x + nB_i*y + nC_i   (== w_i/det)
// inv_zp(x,y) = P*x + Q*y + R
__device__ float4 g_c0[NBATCH * FACES];
__device__ float4 g_c1[NBATCH * FACES];
__device__ float4 g_c2[NBATCH * FACES];
__device__ float4 g_rz[NBATCH * FACES];
__device__ int    g_binCnt[NBINS];          // zero-init at load; raster re-zeros
__device__ int    g_binList[NBINS * BINCAP];

// One thread per (face, tile-slot). Slot 0 also writes the normalized coeffs.
__global__ __launch_bounds__(256) void setup_kernel(const float* __restrict__ faces)
{
    const int gid  = blockIdx.x * 256 + threadIdx.x;   // 0 .. B*F*SLOTS-1
    const int id   = gid >> 4;                          // face id 0..B*F-1
    const int slot = gid & (SLOTS - 1);
    const int b = id >> 12;
    const int f = id & (FACES - 1);

    const float* fv = faces + (size_t)id * 9;
    const float x0 = fv[0], y0 = fv[1], z0 = fv[2];
    const float x1 = fv[3], y1 = fv[4], z1 = fv[5];
    const float x2 = fv[6], y2 = fv[7], z2 = fv[8];

    const float A0 = y1 - y2, B0 = x2 - x1, C0 = x1 * y2 - x2 * y1;
    const float A1 = y2 - y0, B1 = x0 - x2, C1 = x2 * y0 - x0 * y2;
    const float A2 = y0 - y1, B2 = x1 - x0, C2 = x0 * y1 - x1 * y0;
    const float det = C0 + C1 + C2;      // x/y coeffs cancel: det is constant
    if (!(fabsf(det) > TINYF)) return;   // degenerate: never inside, never binned

    if (slot == 0) {
        // only 1/16 of threads pay the MUFU cost
        const float rd  = 1.0f / det;
        const float rz0 = 1.0f / z0, rz1 = 1.0f / z1, rz2 = 1.0f / z2;
        const float nA0 = A0 * rd, nB0 = B0 * rd, nC0 = C0 * rd;
        const float nA1 = A1 * rd, nB1 = B1 * rd, nC1 = C1 * rd;
        const float nA2 = A2 * rd, nB2 = B2 * rd, nC2 = C2 * rd;
        g_c0[id] = make_float4(nA0, nB0, nC0, nA0 * rz0 + nA1 * rz1 + nA2 * rz2);
        g_c1[id] = make_float4(nA1, nB1, nC1, nB0 * rz0 + nB1 * rz1 + nB2 * rz2);
        g_c2[id] = make_float4(nA2, nB2, nC2, nC0 * rz0 + nC1 * rz1 + nC2 * rz2);
        g_rz[id] = make_float4(rz0, rz1, rz2, 0.0f);
    }

    const float xmn = fminf(x0, fminf(x1, x2)), xmx = fmaxf(x0, fmaxf(x1, x2));
    const float ymn = fminf(y0, fminf(y1, y2)), ymx = fmaxf(y0, fmaxf(y1, y2));

    // pixel center xp = (2*px + 1 - IS)/IS  =>  px = (IS*xp + IS-1)/2 ; widen 1px
    int pxlo = (int)ceilf ((xmn * IS + (IS - 1)) * 0.5f) - 1;
    int pxhi = (int)floorf((xmx * IS + (IS - 1)) * 0.5f) + 1;
    int pylo = (int)ceilf ((ymn * IS + (IS - 1)) * 0.5f) - 1;
    int pyhi = (int)floorf((ymx * IS + (IS - 1)) * 0.5f) + 1;
    pxlo = max(pxlo, 0); pxhi = min(pxhi, IS - 1);
    pylo = max(pylo, 0); pyhi = min(pyhi, IS - 1);
    if (pxlo > pxhi || pylo > pyhi) return;

    const int txlo = pxlo >> 3, txhi = pxhi >> 3;
    const int tylo = pylo >> 3, tyhi = pyhi >> 3;
    const int nx = txhi - txlo + 1;
    const int ny = tyhi - tylo + 1;
    if (slot >= nx * ny) return;

    const int tx = txlo + (slot - (slot / nx) * nx);
    const int ty = tylo + slot / nx;

    // Conservative cull in UNNORMALIZED space (no division):
    const float s = (det > 0.0f) ? 1.0f : -1.0f;
    const float sA0 = s * A0, sB0 = s * B0, sC0 = s * C0;
    const float sA1 = s * A1, sB1 = s * B1, sC1 = s * C1;
    const float sA2 = s * A2, sB2 = s * B2, sC2 = s * C2;

    const float txlo_c = (2.0f * (tx * TILE)            + 1.0f - IS) * (1.0f / IS);
    const float txhi_c = (2.0f * (tx * TILE + TILE - 1) + 1.0f - IS) * (1.0f / IS);
    const float tylo_c = (2.0f * (ty * TILE)            + 1.0f - IS) * (1.0f / IS);
    const float tyhi_c = (2.0f * (ty * TILE + TILE - 1) + 1.0f - IS) * (1.0f / IS);

    const float m0 = fmaxf(sA0 * txlo_c, sA0 * txhi_c) + fmaxf(sB0 * tylo_c, sB0 * tyhi_c) + sC0;
    const float m1 = fmaxf(sA1 * txlo_c, sA1 * txhi_c) + fmaxf(sB1 * tylo_c, sB1 * tyhi_c) + sC1;
    const float m2 = fmaxf(sA2 * txlo_c, sA2 * txhi_c) + fmaxf(sB2 * tylo_c, sB2 * tyhi_c) + sC2;

    const float ad  = fabsf(det);
    const float t0 = -1e-5f * (fabsf(A0) + fabsf(B0)) - 1e-6f * ad;
    const float t1 = -1e-5f * (fabsf(A1) + fabsf(B1)) - 1e-6f * ad;
    const float t2 = -1e-5f * (fabsf(A2) + fabsf(B2)) - 1e-6f * ad;
    if (m0 < t0 || m1 < t1 || m2 < t2) return;   // some edge fully excludes tile

    const int bin = (b * NTX + ty) * NTX + tx;
    const int pos = atomicAdd(&g_binCnt[bin], 1);
    if (pos < BINCAP) g_binList[bin * BINCAP + pos] = f;
}

// 8 warps per CTA. Each warp owns one 8x4 HALF-tile; 1 pixel per lane.
// Winner selection is a branchless max over 64-bit keys:
//   key = (float_bits(iz) << 32) | (4095 - f)     if valid, else 0
// float bits are monotonic for iz > 0, so max(key) = (max iz, tie -> min f).
__global__ __launch_bounds__(256) void raster_kernel(
    const float* __restrict__ tex,
    float* __restrict__ out)
{
    __shared__ float4   sc[8][32][3];
    __shared__ unsigned slo[8][32];     // pre-flipped: 4095 - f

    const int tid  = threadIdx.x;
    const int warp = tid >> 5;
    const int lane = tid & 31;
    const int b    = blockIdx.z;

    const int tilex = blockIdx.x * 4 + (warp & 3);
    const int tiley = blockIdx.y;
    const int half  = warp >> 2;                       // 0: rows 0-3, 1: rows 4-7

    const int px = tilex * TILE + (lane & 7);
    const int py = tiley * TILE + half * 4 + (lane >> 3);

    const float xp = (2.0f * px + 1.0f - IS) * (1.0f / IS);
    const float yp = (2.0f * py + 1.0f - IS) * (1.0f / IS);

    const int bin = (b * NTX + tiley) * NTX + tilex;
    int n = 0;
    if (lane == 0) n = min(g_binCnt[bin], BINCAP);
    n = __shfl_sync(0xffffffffu, n, 0);
    __syncthreads();                                   // both halves have read the count
    if (half == 0 && lane == 0) g_binCnt[bin] = 0;     // reset for next graph replay

    // init: far-clip boundary; low word all-ones so iz == 1/FAR still loses
    const u64 KINIT = ((u64)__float_as_uint(1.0f / FAR_P) << 32) | 0xFFFFFFFFull;
    u64 bestA = KINIT, bestB = KINIT;

    for (int start = 0; start < n; start += 32) {
        const int cnt = min(32, n - start);
        if (lane < cnt) {
            const int f  = g_binList[bin * BINCAP + start + lane];
            const int id = b * FACES + f;
            sc[warp][lane][0] = g_c0[id];
            sc[warp][lane][1] = g_c1[id];
            sc[warp][lane][2] = g_c2[id];
            slo[warp][lane]   = (FACES - 1) - f;
        }
        __syncwarp();

        #pragma unroll 4
        for (int c = 0; c < cnt; c++) {
            const float4 a0 = sc[warp][c][0];
            const float4 a1 = sc[warp][c][1];
            const float4 a2 = sc[warp][c][2];
            const float n0 = fmaf(xp, a0.x, fmaf(yp, a0.y, a0.z));
            const float n1 = fmaf(xp, a1.x, fmaf(yp, a1.y, a1.z));
            const float n2 = fmaf(xp, a2.x, fmaf(yp, a2.y, a2.z));
            const float iz = fmaf(xp, a0.w, fmaf(yp, a1.w, a2.w));
            const float mn = fminf(n0, fminf(n1, n2));
            const bool ok = (mn > 0.0f) & (iz > (1.0f / FAR_P)) & (iz < (1.0f / NEAR_P));
            const u64 key = ok ? (((u64)__float_as_uint(iz) << 32) | slo[warp][c]) : 0ull;
            if (c & 1) { if (key > bestB) bestB = key; }
            else       { if (key > bestA) bestA = key; }
        }
        __syncwarp();
    }

    const u64 best = (bestB > bestA) ? bestB : bestA;
    const unsigned lo = (unsigned)best;
    const int bestF = (lo == 0xFFFFFFFFu) ? -1 : (FACES - 1) - (int)lo;

    // -------- shading from precomputed coefficients --------
    float r = 0.f, g = 0.f, bl = 0.f, alpha = 0.f, depth = FAR_P;
    if (bestF >= 0) {
        const int idw = b * FACES + bestF;
        const float4 a0 = g_c0[idw];
        const float4 a1 = g_c1[idw];
        const float4 a2 = g_c2[idw];
        const float4 rz = g_rz[idw];

        float n0 = fmaf(xp, a0.x, fmaf(yp, a0.y, a0.z));
        float n1 = fmaf(xp, a1.x, fmaf(yp, a1.y, a1.z));
        float n2 = fmaf(xp, a2.x, fmaf(yp, a2.y, a2.z));
        n0 = fminf(fmaxf(n0, 0.f), 1.f);
        n1 = fminf(fmaxf(n1, 0.f), 1.f);
        n2 = fminf(fmaxf(n2, 0.f), 1.f);
        float s = n0 + n1 + n2;
        if (!(s > TINYF)) s = 1.0f;
        const float rs = 1.0f / s;
        const float u0 = n0 * rs * rz.x;
        const float u1 = n1 * rs * rz.y;
        const float u2 = n2 * rs * rz.z;
        float invz = u0 + u1 + u2;
        if (!(fabsf(invz) > TINYF)) invz = 1.0f;
        const float zp = 1.0f / invz;
        depth = zp;
        alpha = 1.0f;

        const float hi = 3.0f - EPSV;   // T-1-EPS, T=4
        const float zp3 = 3.0f * zp;
        const float t0 = fminf(fmaxf(u0 * zp3, 0.f), hi);
        const float t1 = fminf(fmaxf(u1 * zp3, 0.f), hi);
        const float t2 = fminf(fmaxf(u2 * zp3, 0.f), hi);
        const float l0f = floorf(t0), l1f = floorf(t1), l2f = floorf(t2);
        const float f0 = t0 - l0f, f1 = t1 - l1f, f2 = t2 - l2f;
        const int l0 = (int)l0f, l1 = (int)l1f, l2 = (int)l2f;

        const float* tp = tex + (size_t)idw * 192;
        #pragma unroll
        for (int d0 = 0; d0 < 2; d0++) {
            const float wx = d0 ? f0 : 1.0f - f0;
            #pragma unroll
            for (int d1 = 0; d1 < 2; d1++) {
                const float wy = wx * (d1 ? f1 : 1.0f - f1);
                #pragma unroll
                for (int d2 = 0; d2 < 2; d2++) {
                    const float wgt = wy * (d2 ? f2 : 1.0f - f2);
                    const int idx = ((l0 + d0) * 16 + (l1 + d1) * 4 + (l2 + d2)) * 3;
                    r  += wgt * tp[idx + 0];
                    g  += wgt * tp[idx + 1];
                    bl += wgt * tp[idx + 2];
                }
            }
        }
    }
    float* o = out + (((size_t)b * IS + py) * IS + px) * 5;
    o[0] = r; o[1] = g; o[2] = bl; o[3] = alpha; o[4] = depth;
}

extern "C" void kernel_launch(void* const* d_in, const int* in_sizes, int n_in,
                              void* d_out, int out_size)
{
    const float* faces = (const float*)d_in[0];
    const float* tex   = (const float*)d_in[1];
    float* out         = (float*)d_out;

    setup_kernel<<<(NBATCH * FACES * SLOTS) / 256, 256>>>(faces);
    dim3 grid(NTX / 4, NTX, NBATCH);   // 8 x 32 x 4 = 1024 CTAs, 8 half-tiles each
    raster_kernel<<<grid, 256>>>(tex, out);
}